// round 4
// baseline (speedup 1.0000x reference)
#include <cuda_runtime.h>
#include <cstdint>

#define LSEQ 2048
#define D    64

// Transposed Q (m=0..31), K (m=32..63), Er (m=64): each [64][2048]
__device__ float g_T[65 * D * LSEQ];
__device__ float g_IZ[32 * LSEQ];
__device__ float g_ctx_scratch[2 * 16 * 2048 * 64];

typedef unsigned long long ull;

__device__ __forceinline__ int swz(int s) { return s ^ ((s >> 3) & 7); }
__device__ __forceinline__ ull pk2(float lo, float hi) {
    ull r; asm("mov.b64 %0, {%1, %2};" : "=l"(r) : "f"(lo), "f"(hi)); return r;
}
__device__ __forceinline__ void up2(ull v, float& lo, float& hi) {
    asm("mov.b64 {%0, %1}, %2;" : "=f"(lo), "=f"(hi) : "l"(v));
}
__device__ __forceinline__ void fma2(ull& a, ull x, ull y) {
    asm("fma.rn.f32x2 %0, %1, %2, %0;" : "+l"(a) : "l"(x), "l"(y));
}

// ---------------- transpose [2048][64] -> [64][2048] ----------------
__global__ void transpose_kernel(const float* __restrict__ Q,
                                 const float* __restrict__ K,
                                 const float* __restrict__ Er)
{
    __shared__ float sm[128 * 65];
    const int m  = blockIdx.x;
    const int r0 = blockIdx.y * 128;
    const float* src;
    if (m < 32)      src = Q  + (size_t)m        * LSEQ * D;
    else if (m < 64) src = K  + (size_t)(m - 32) * LSEQ * D;
    else             src = Er;
    float* dst = g_T + (size_t)m * D * LSEQ;
    const int t = threadIdx.x;
    for (int i = t; i < 128 * 16; i += 256) {
        int r = i >> 4, c = i & 15;
        float4 v = ((const float4*)(src + (size_t)(r0 + r) * D))[c];
        float* p = sm + r * 65 + 4 * c;
        p[0] = v.x; p[1] = v.y; p[2] = v.z; p[3] = v.w;
    }
    __syncthreads();
    for (int i = t; i < 64 * 32; i += 256) {
        int d = i >> 5, jj = i & 31;
        float4 v;
        v.x = sm[(4 * jj + 0) * 65 + d];
        v.y = sm[(4 * jj + 1) * 65 + d];
        v.z = sm[(4 * jj + 2) * 65 + d];
        v.w = sm[(4 * jj + 3) * 65 + d];
        ((float4*)(dst + (size_t)d * LSEQ + r0))[jj] = v;
    }
}

// ============ Kernel A: S = Q(K+Er)/8, exp, unnormalized store, 1/z ========
// block: 128 thr, q-tile 64, k-tile 128, 8q x 8k per thread.
__global__ void __launch_bounds__(128, 2)
score_kernel(float* __restrict__ attn)
{
    extern __shared__ float sm[];
    float* smQ = sm;                 // [64][64]
    float* smK = sm + 4096;          // [64][128]
    float* smE = sm + 12288;         // [64][192]

    const int qt = 31 - (int)blockIdx.x;
    const int bh = blockIdx.y;
    const int q0 = qt * 64;
    const int t  = threadIdx.x;
    const int tq = t >> 4;           // 0..7
    const int tk = t & 15;           // 0..15

    const float* QT = g_T + (size_t)bh * (D * LSEQ);
    const float* KT = g_T + (size_t)(32 + bh) * (D * LSEQ);
    const float* ET = g_T + (size_t)64 * (D * LSEQ);
    float* attng = attn + (size_t)bh * LSEQ * LSEQ;

    for (int i = t; i < 64 * 16; i += 128) {
        int d = i >> 4, s = i & 15;
        *((float4*)(smQ + d * 64 + 4 * s)) =
            *((const float4*)(QT + (size_t)d * LSEQ + q0 + 4 * s));
    }

    float zrun[8];
#pragma unroll
    for (int i = 0; i < 8; i++) zrun[i] = 0.f;

    const int ktmax = q0 >> 7;
    const int sE = 2 * (tk - tq) + 14;

    for (int kt = 0; kt <= ktmax; kt++) {
        const int k0 = kt * 128;
        __syncthreads();
        for (int i = t; i < 2048; i += 128) {       // K tile
            int d = i >> 5, s = i & 31;
            *((float4*)(smK + d * 128 + 4 * swz(s))) =
                *((const float4*)(KT + (size_t)d * LSEQ + k0 + 4 * s));
        }
        const int ebase = 1984 + k0 - q0;           // >= 0 always
        for (int i = t; i < 3072; i += 128) {       // Er band tile
            int d = i / 48, s = i - d * 48;
            int e = ebase + 4 * s;
            const float* er = ET + (size_t)d * LSEQ;
            float4 v;
            if (e + 3 < LSEQ) v = *((const float4*)(er + e));
            else {
                v.x = (e + 0 < LSEQ) ? er[e + 0] : 0.f;
                v.y = (e + 1 < LSEQ) ? er[e + 1] : 0.f;
                v.z = (e + 2 < LSEQ) ? er[e + 2] : 0.f;
                v.w = (e + 3 < LSEQ) ? er[e + 3] : 0.f;
            }
            *((float4*)(smE + d * 192 + 4 * swz(s))) = v;
        }
        __syncthreads();

        ull acc[8][4];
#pragma unroll
        for (int i = 0; i < 8; i++)
#pragma unroll
            for (int jp = 0; jp < 4; jp++) acc[i][jp] = 0ull;

#pragma unroll 4
        for (int d = 0; d < 64; d++) {
            const float* qd = smQ + d * 64;
            const float* kd = smK + d * 128;
            const float* ed = smE + d * 192;
            float4 qa = *((const float4*)(qd + 8 * tq));
            float4 qb = *((const float4*)(qd + 8 * tq + 4));
            float4 ka = *((const float4*)(kd + 4 * swz(2 * tk)));
            float4 kb = *((const float4*)(kd + 4 * swz(2 * tk + 1)));
            float4 e0 = *((const float4*)(ed + 4 * swz(sE + 0)));
            float4 e1 = *((const float4*)(ed + 4 * swz(sE + 1)));
            float4 e2 = *((const float4*)(ed + 4 * swz(sE + 2)));
            float4 e3 = *((const float4*)(ed + 4 * swz(sE + 3)));
            float w[16] = {e0.x, e0.y, e0.z, e0.w, e1.x, e1.y, e1.z, e1.w,
                           e2.x, e2.y, e2.z, e2.w, e3.x, e3.y, e3.z, e3.w};
            ull kp[4] = {pk2(ka.x, ka.y), pk2(ka.z, ka.w),
                         pk2(kb.x, kb.y), pk2(kb.z, kb.w)};
            ull ep[14];
#pragma unroll
            for (int x = 0; x < 14; x++) ep[x] = pk2(w[x], w[x + 1]);
            float qv[8] = {qa.x, qa.y, qa.z, qa.w, qb.x, qb.y, qb.z, qb.w};
#pragma unroll
            for (int i = 0; i < 8; i++) {
                ull qq = pk2(qv[i], qv[i]);
#pragma unroll
                for (int jp = 0; jp < 4; jp++) {
                    fma2(acc[i][jp], qq, kp[jp]);
                    fma2(acc[i][jp], qq, ep[7 - i + 2 * jp]);
                }
            }
        }

        const bool diag = (kt == ktmax);
        const int kg0 = k0 + 8 * tk;
#pragma unroll
        for (int i = 0; i < 8; i++) {
            const int q = q0 + 8 * tq + i;
            float p[8];
#pragma unroll
            for (int jp = 0; jp < 4; jp++) {
                float lo, hi; up2(acc[i][jp], lo, hi);
                p[2 * jp]     = __expf(lo * 0.125f);
                p[2 * jp + 1] = __expf(hi * 0.125f);
            }
            if (diag) {
#pragma unroll
                for (int j = 0; j < 8; j++) if (kg0 + j > q) p[j] = 0.f;
            }
            zrun[i] += ((p[0] + p[1]) + (p[2] + p[3])) + ((p[4] + p[5]) + (p[6] + p[7]));
            float* dst = attng + (size_t)q * LSEQ + kg0;
            *((float4*)dst)       = make_float4(p[0], p[1], p[2], p[3]);
            *((float4*)(dst + 4)) = make_float4(p[4], p[5], p[6], p[7]);
        }
    }

#pragma unroll
    for (int i = 0; i < 8; i++) {
#pragma unroll
        for (int off = 8; off >= 1; off >>= 1)
            zrun[i] += __shfl_xor_sync(0xffffffffu, zrun[i], off);
    }
    if (tk == 0) {
#pragma unroll
        for (int i = 0; i < 8; i++)
            g_IZ[bh * LSEQ + q0 + 8 * tq + i] = 1.f / zrun[i];
    }
}

// ============ Kernel B: normalize attn in place + ctx = P·V + zero-fill ====
__global__ void __launch_bounds__(128, 3)
pv_kernel(const float* __restrict__ V, float* __restrict__ ctx,
          float* __restrict__ attn)
{
    extern __shared__ float sm[];
    float* smP  = sm;                // [64][128]
    float* smV  = sm + 8192;         // [128][64]
    float* smIZ = sm + 16384;        // [64]

    if (ctx == nullptr) ctx = g_ctx_scratch;
    const int qt = 31 - (int)blockIdx.x;
    const int bh = blockIdx.y;
    const int q0 = qt * 64;
    const int t  = threadIdx.x;
    const int tq = t >> 4;           // 0..7 (8 q rows)
    const int td = t & 15;           // 0..15 (4 d cols)

    const float* Vg = V + (size_t)bh * LSEQ * D;
    float* attng = attn + (size_t)bh * LSEQ * LSEQ;
    float* ctxg  = ctx  + (size_t)bh * LSEQ * D;

    if (t < 64) smIZ[t] = g_IZ[bh * LSEQ + q0 + t];

    ull cacc[8][2];
#pragma unroll
    for (int i = 0; i < 8; i++) { cacc[i][0] = 0ull; cacc[i][1] = 0ull; }

    const int ktmax = q0 >> 7;
    for (int kt = 0; kt <= ktmax; kt++) {
        const int k0 = kt * 128;
        __syncthreads();
        for (int i = t; i < 2048; i += 128) {       // V tile [k][d]
            int k = i >> 4, s = i & 15;
            *((float4*)(smV + k * 64 + 4 * s)) =
                *((const float4*)(Vg + (size_t)(k0 + k) * D + 4 * s));
        }
        for (int i = t; i < 2048; i += 128) {       // P tile: read, scale, wb
            int r = i >> 5, c = i & 31;
            size_t gi = (size_t)(q0 + r) * LSEQ + k0 + 4 * c;
            float4 pv = *((const float4*)(attng + gi));
            float iz = smIZ[r];
            pv.x *= iz; pv.y *= iz; pv.z *= iz; pv.w *= iz;
            *((float4*)(attng + gi)) = pv;
            *((float4*)(smP + r * 128 + 4 * c)) = pv;
        }
        __syncthreads();

#pragma unroll 4
        for (int kk = 0; kk < 32; kk++) {           // 4 k per iter
            ull vp[4][2];
#pragma unroll
            for (int x = 0; x < 4; x++) {
                float4 vf = *((const float4*)(smV + (4 * kk + x) * 64 + 4 * td));
                vp[x][0] = pk2(vf.x, vf.y);
                vp[x][1] = pk2(vf.z, vf.w);
            }
#pragma unroll
            for (int i = 0; i < 8; i++) {
                float4 pf = *((const float4*)(smP + (8 * tq + i) * 128 + 4 * kk));
                float pv4[4] = {pf.x, pf.y, pf.z, pf.w};
#pragma unroll
                for (int x = 0; x < 4; x++) {
                    ull pb = pk2(pv4[x], pv4[x]);
                    fma2(cacc[i][0], pb, vp[x][0]);
                    fma2(cacc[i][1], pb, vp[x][1]);
                }
            }
        }
    }

    // zero-fill the future columns of this q-slab
    const int kend = (ktmax + 1) * 128;
    const int nz = (LSEQ - kend) >> 2;
    if (nz > 0) {
        const float4 z4 = make_float4(0.f, 0.f, 0.f, 0.f);
        for (int i = t; i < 64 * nz; i += 128) {
            int r = i / nz, c = i - r * nz;
            *((float4*)(attng + (size_t)(q0 + r) * LSEQ + kend + 4 * c)) = z4;
        }
    }

    // write context (already normalized since P was normalized)
#pragma unroll
    for (int i = 0; i < 8; i++) {
        const int q = q0 + 8 * tq + i;
        float a, b, c2, d2;
        up2(cacc[i][0], a, b); up2(cacc[i][1], c2, d2);
        *((float4*)(ctxg + (size_t)q * D + 4 * td)) = make_float4(a, b, c2, d2);
    }
}

extern "C" void kernel_launch(void* const* d_in, const int* in_sizes, int n_in,
                              void* d_out, int out_size) {
    const float* Q  = (const float*)d_in[0];
    const float* K  = (const float*)d_in[1];
    const float* V  = (const float*)d_in[2];
    const float* Er = (const float*)d_in[4];

    const long long CTXN = (long long)2 * 16 * 2048 * 64;
    const long long ATTN = (long long)2 * 16 * 2048 * 2048;

    float* out = (float*)d_out;
    float* ctx; float* attn;
    if ((long long)out_size >= CTXN + ATTN) { ctx = out; attn = out + CTXN; }
    else if ((long long)out_size == ATTN)   { ctx = nullptr; attn = out; }
    else                                    { ctx = out; attn = out; }

    transpose_kernel<<<dim3(65, 16), 256>>>(Q, K, Er);

    const int smA = (4096 + 8192 + 12288) * (int)sizeof(float);   // 96 KB
    cudaFuncSetAttribute(score_kernel,
                         cudaFuncAttributeMaxDynamicSharedMemorySize, smA);
    score_kernel<<<dim3(32, 32), 128, smA>>>(attn);

    const int smB = (8192 + 8192 + 64) * (int)sizeof(float);      // ~64 KB
    cudaFuncSetAttribute(pv_kernel,
                         cudaFuncAttributeMaxDynamicSharedMemorySize, smB);
    pv_kernel<<<dim3(32, 32), 128, smB>>>(V, ctx, attn);
}

// round 6
// speedup vs baseline: 1.1535x; 1.1535x over previous
#include <cuda_runtime.h>
#include <cuda_bf16.h>
#include <cstdint>

#define LSEQ 2048
typedef unsigned long long ull;

__device__ float g_IZ[32 * LSEQ];
__device__ float g_ctx_scratch[2 * 16 * 2048 * 64];

// ---- smem byte offsets for score kernel (pitch 72 bf16 = 144B rows) ----
#define OQH 0
#define OQL 18432
#define OKH 36864
#define OKL 55296
#define OEH 73728
#define OEL 101376
#define ORS 129024
#define RSP 196
#define SMEM_TOT (229376)

__device__ __forceinline__ uint32_t smem_u32(const void* p) {
    uint32_t a;
    asm("{ .reg .u64 t; cvta.to.shared.u64 t, %1; cvt.u32.u64 %0, t; }" : "=r"(a) : "l"(p));
    return a;
}
__device__ __forceinline__ void ldmA(uint32_t* a, uint32_t addr) {
    asm volatile("ldmatrix.sync.aligned.m8n8.x4.shared.b16 {%0,%1,%2,%3}, [%4];"
        : "=r"(a[0]), "=r"(a[1]), "=r"(a[2]), "=r"(a[3]) : "r"(addr));
}
__device__ __forceinline__ void ldmB(uint32_t* b, uint32_t addr) {
    asm volatile("ldmatrix.sync.aligned.m8n8.x2.shared.b16 {%0,%1}, [%2];"
        : "=r"(b[0]), "=r"(b[1]) : "r"(addr));
}
__device__ __forceinline__ void mmabf(float* d, const uint32_t* a, const uint32_t* b) {
    asm volatile("mma.sync.aligned.m16n8k16.row.col.f32.bf16.bf16.f32 "
        "{%0,%1,%2,%3}, {%4,%5,%6,%7}, {%8,%9}, {%0,%1,%2,%3};"
        : "+f"(d[0]), "+f"(d[1]), "+f"(d[2]), "+f"(d[3])
        : "r"(a[0]), "r"(a[1]), "r"(a[2]), "r"(a[3]), "r"(b[0]), "r"(b[1]));
}
__device__ __forceinline__ uint32_t pkbf(float a, float b) {
    __nv_bfloat162 h = __floats2bfloat162_rn(a, b);
    return *(uint32_t*)&h;
}
__device__ __forceinline__ void split72(char* hi, char* lo, int r, int c4, float4 v) {
    float hx = __bfloat162float(__float2bfloat16(v.x));
    float hy = __bfloat162float(__float2bfloat16(v.y));
    float hz = __bfloat162float(__float2bfloat16(v.z));
    float hw = __bfloat162float(__float2bfloat16(v.w));
    int off = r * 144 + c4 * 8;
    *(uint2*)(hi + off) = make_uint2(pkbf(v.x, v.y), pkbf(v.z, v.w));
    *(uint2*)(lo + off) = make_uint2(pkbf(v.x - hx, v.y - hy), pkbf(v.z - hz, v.w - hw));
}

// ================= Kernel A: mma.sync scores -> unnormalized exp + 1/z =====
__global__ void __launch_bounds__(256, 1)
score_mma(const float* __restrict__ Q, const float* __restrict__ K,
          const float* __restrict__ Er, float* __restrict__ attn)
{
    extern __shared__ char sm[];
    const uint32_t sb = smem_u32(sm);
    float* Rs = (float*)(sm + ORS);

    const int qt = 15 - (int)blockIdx.x;
    const int bh = blockIdx.y;
    const int q0 = qt * 128;
    const int t = threadIdx.x;
    const int wid = t >> 5, lane = t & 31;
    const int wm = wid >> 1, wn = wid & 1;

    const float* Qg = Q + (size_t)bh * LSEQ * 64;
    const float* Kg = K + (size_t)bh * LSEQ * 64;
    float* attng = attn + (size_t)bh * LSEQ * LSEQ;

    // Q tile (split hi/lo)
    for (int i = t; i < 2048; i += 256) {
        int r = i >> 4, c4 = i & 15;
        split72(sm + OQH, sm + OQL, r, c4,
                *((const float4*)(Qg + (size_t)(q0 + r) * 64 + 4 * c4)));
    }
    __syncthreads();

    // A fragments (persistent): [mt][ks][4]
    const int arow = (lane & 7) + 8 * ((lane >> 3) & 1);
    const int acolB = 16 * (lane >> 4);
    uint32_t AH[2][4][4], AL[2][4][4];
#pragma unroll
    for (int mt = 0; mt < 2; mt++)
#pragma unroll
        for (int ks = 0; ks < 4; ks++) {
            uint32_t ro = (uint32_t)((32 * wm + 16 * mt + arow) * 144 + ks * 32 + acolB);
            ldmA(AH[mt][ks], sb + OQH + ro);
            ldmA(AL[mt][ks], sb + OQL + ro);
        }

    const int browB = (lane & 7) * 144;
    const int bcolB = 16 * ((lane >> 3) & 1);
    float zacc[2][2] = {{0.f, 0.f}, {0.f, 0.f}};

    for (int kt = 0; kt <= qt; kt++) {
        const int k0 = kt * 128;
        __syncthreads();
        for (int i = t; i < 2048; i += 256) {                 // K tile
            int r = i >> 4, c4 = i & 15;
            split72(sm + OKH, sm + OKL, r, c4,
                    *((const float4*)(Kg + (size_t)(k0 + r) * 64 + 4 * c4)));
        }
#pragma unroll 1
        for (int kh = 0; kh < 2; kh++) {
            const int vlo = q0 - k0 - 64 * kh - 63;
            for (int i = t; i < 3072; i += 256) {             // E~ window (192 rows)
                int j = i >> 4, c4 = i & 15;
                int e = 2047 - (vlo + j);
                float4 v = make_float4(0.f, 0.f, 0.f, 0.f);
                if (e >= 0 && e < LSEQ)
                    v = *((const float4*)(Er + (size_t)e * 64 + 4 * c4));
                split72(sm + OEH, sm + OEL, j, c4, v);
            }
            __syncthreads();

            // R = Q * E~^T  (192 cols; this warp: 96*wn .. +96)
#pragma unroll 1
            for (int nt = 0; nt < 12; nt++) {
                float racc[2][4] = {{0.f, 0.f, 0.f, 0.f}, {0.f, 0.f, 0.f, 0.f}};
                const uint32_t nb = (uint32_t)((96 * wn + 8 * nt) * 144) + browB + bcolB;
#pragma unroll
                for (int ks = 0; ks < 4; ks++) {
                    uint32_t BH[2], BL[2];
                    ldmB(BH, sb + OEH + nb + ks * 32);
                    ldmB(BL, sb + OEL + nb + ks * 32);
#pragma unroll
                    for (int mt = 0; mt < 2; mt++) {
                        mmabf(racc[mt], AH[mt][ks], BH);
                        mmabf(racc[mt], AH[mt][ks], BL);
                        mmabf(racc[mt], AL[mt][ks], BH);
                    }
                }
#pragma unroll
                for (int mt = 0; mt < 2; mt++) {
                    int q = 32 * wm + 16 * mt + (lane >> 2);
                    int c = 96 * wn + 8 * nt + 2 * (lane & 3);
                    *((float2*)(Rs + q * RSP + c)) = make_float2(racc[mt][0], racc[mt][1]);
                    *((float2*)(Rs + (q + 8) * RSP + c)) = make_float2(racc[mt][2], racc[mt][3]);
                }
            }

            // S half = Q * K^T (64 cols; this warp: 64*kh + 32*wn .. +32)
            float sacc[2][4][4];
#pragma unroll
            for (int mt = 0; mt < 2; mt++)
#pragma unroll
                for (int nt = 0; nt < 4; nt++)
#pragma unroll
                    for (int r = 0; r < 4; r++) sacc[mt][nt][r] = 0.f;
#pragma unroll
            for (int nt = 0; nt < 4; nt++) {
                const uint32_t nb = (uint32_t)((64 * kh + 32 * wn + 8 * nt) * 144) + browB + bcolB;
#pragma unroll
                for (int ks = 0; ks < 4; ks++) {
                    uint32_t BH[2], BL[2];
                    ldmB(BH, sb + OKH + nb + ks * 32);
                    ldmB(BL, sb + OKL + nb + ks * 32);
#pragma unroll
                    for (int mt = 0; mt < 2; mt++) {
                        mmabf(sacc[mt][nt], AH[mt][ks], BH);
                        mmabf(sacc[mt][nt], AH[mt][ks], BL);
                        mmabf(sacc[mt][nt], AL[mt][ks], BH);
                    }
                }
            }
            __syncthreads();   // Rs fully written

            // epilogue
            const bool diag = (kt == qt);
#pragma unroll
            for (int mt = 0; mt < 2; mt++) {
#pragma unroll
                for (int nt = 0; nt < 4; nt++) {
                    int kloc = 32 * wn + 8 * nt + 2 * (lane & 3);
                    int kg = k0 + 64 * kh + kloc;
#pragma unroll
                    for (int rh = 0; rh < 2; rh++) {
                        int q = 32 * wm + 16 * mt + 8 * rh + (lane >> 2);
                        int qg = q0 + q;
                        const float* rr = Rs + q * RSP + q - kloc + 63;
                        float s0 = (sacc[mt][nt][2 * rh] + rr[0]) * 0.125f;
                        float s1 = (sacc[mt][nt][2 * rh + 1] + rr[-1]) * 0.125f;
                        float p0 = __expf(s0), p1 = __expf(s1);
                        if (diag) {
                            if (kg > qg) p0 = 0.f;
                            if (kg + 1 > qg) p1 = 0.f;
                        }
                        zacc[mt][rh] += p0 + p1;
                        *((float2*)(attng + (size_t)qg * LSEQ + kg)) = make_float2(p0, p1);
                    }
                }
            }
            __syncthreads();   // epilogue reads done before E~/Rs overwrite
        }
    }

    // z reduce: quad -> smem -> combine warp_n halves
#pragma unroll
    for (int mt = 0; mt < 2; mt++)
#pragma unroll
        for (int rh = 0; rh < 2; rh++) {
            float v = zacc[mt][rh];
            v += __shfl_xor_sync(0xffffffffu, v, 1);
            v += __shfl_xor_sync(0xffffffffu, v, 2);
            zacc[mt][rh] = v;
        }
    __syncthreads();
    float* zb = Rs;
    if ((lane & 3) == 0) {
#pragma unroll
        for (int mt = 0; mt < 2; mt++)
#pragma unroll
            for (int rh = 0; rh < 2; rh++) {
                int row = 32 * wm + 16 * mt + 8 * rh + (lane >> 2);
                zb[row * 2 + wn] = zacc[mt][rh];
            }
    }
    __syncthreads();
    if (t < 128)
        g_IZ[bh * LSEQ + q0 + t] = 1.f / (zb[2 * t] + zb[2 * t + 1]);
}

// ================= Kernel B: normalize + PV (proven) =======================
__device__ __forceinline__ ull pk2(float lo, float hi) {
    ull r; asm("mov.b64 %0, {%1, %2};" : "=l"(r) : "f"(lo), "f"(hi)); return r;
}
__device__ __forceinline__ void up2(ull v, float& lo, float& hi) {
    asm("mov.b64 {%0, %1}, %2;" : "=f"(lo), "=f"(hi) : "l"(v));
}
__device__ __forceinline__ void fma2(ull& a, ull x, ull y) {
    asm("fma.rn.f32x2 %0, %1, %2, %0;" : "+l"(a) : "l"(x), "l"(y));
}

__global__ void __launch_bounds__(128, 3)
pv_kernel(const float* __restrict__ V, float* __restrict__ ctx, float* __restrict__ attn)
{
    extern __shared__ float smf[];
    float* smP = smf;
    float* smV = smf + 8192;
    float* smIZ = smf + 16384;
    if (ctx == nullptr) ctx = g_ctx_scratch;
    const int qt = 31 - (int)blockIdx.x;
    const int bh = blockIdx.y;
    const int q0 = qt * 64;
    const int t = threadIdx.x;
    const int tq = t >> 4, td = t & 15;
    const float* Vg = V + (size_t)bh * LSEQ * 64;
    float* attng = attn + (size_t)bh * LSEQ * LSEQ;
    float* ctxg = ctx + (size_t)bh * LSEQ * 64;
    if (t < 64) smIZ[t] = g_IZ[bh * LSEQ + q0 + t];
    ull cacc[8][2];
#pragma unroll
    for (int i = 0; i < 8; i++) { cacc[i][0] = 0ull; cacc[i][1] = 0ull; }
    const int ktmax = q0 >> 7;
    for (int kt = 0; kt <= ktmax; kt++) {
        const int k0 = kt * 128;
        __syncthreads();
        for (int i = t; i < 2048; i += 128) {
            int k = i >> 4, s = i & 15;
            *((float4*)(smV + k * 64 + 4 * s)) =
                *((const float4*)(Vg + (size_t)(k0 + k) * 64 + 4 * s));
        }
        for (int i = t; i < 2048; i += 128) {
            int r = i >> 5, c = i & 31;
            size_t gi = (size_t)(q0 + r) * LSEQ + k0 + 4 * c;
            float4 pv = *((const float4*)(attng + gi));
            float iz = smIZ[r];
            pv.x *= iz; pv.y *= iz; pv.z *= iz; pv.w *= iz;
            *((float4*)(attng + gi)) = pv;
            *((float4*)(smP + r * 128 + 4 * c)) = pv;
        }
        __syncthreads();
#pragma unroll 4
        for (int kk = 0; kk < 32; kk++) {
            ull vp[4][2];
#pragma unroll
            for (int x = 0; x < 4; x++) {
                float4 vf = *((const float4*)(smV + (4 * kk + x) * 64 + 4 * td));
                vp[x][0] = pk2(vf.x, vf.y);
                vp[x][1] = pk2(vf.z, vf.w);
            }
#pragma unroll
            for (int i = 0; i < 8; i++) {
                float4 pf = *((const float4*)(smP + (8 * tq + i) * 128 + 4 * kk));
                float pv4[4] = {pf.x, pf.y, pf.z, pf.w};
#pragma unroll
                for (int x = 0; x < 4; x++) {
                    ull pb = pk2(pv4[x], pv4[x]);
                    fma2(cacc[i][0], pb, vp[x][0]);
                    fma2(cacc[i][1], pb, vp[x][1]);
                }
            }
        }
    }
    const int kend = (ktmax + 1) * 128;
    const int nz = (LSEQ - kend) >> 2;
    if (nz > 0) {
        const float4 z4 = make_float4(0.f, 0.f, 0.f, 0.f);
        for (int i = t; i < 64 * nz; i += 128) {
            int r = i / nz, c = i - r * nz;
            *((float4*)(attng + (size_t)(q0 + r) * LSEQ + kend + 4 * c)) = z4;
        }
    }
#pragma unroll
    for (int i = 0; i < 8; i++) {
        const int q = q0 + 8 * tq + i;
        float a, b, c2, d2;
        up2(cacc[i][0], a, b); up2(cacc[i][1], c2, d2);
        *((float4*)(ctxg + (size_t)q * 64 + 4 * td)) = make_float4(a, b, c2, d2);
    }
}

extern "C" void kernel_launch(void* const* d_in, const int* in_sizes, int n_in,
                              void* d_out, int out_size) {
    const float* Q  = (const float*)d_in[0];
    const float* K  = (const float*)d_in[1];
    const float* V  = (const float*)d_in[2];
    const float* Er = (const float*)d_in[4];

    const long long CTXN = (long long)2 * 16 * 2048 * 64;
    const long long ATTN = (long long)2 * 16 * 2048 * 2048;
    float* out = (float*)d_out;
    float* ctx; float* attn;
    if ((long long)out_size >= CTXN + ATTN) { ctx = out; attn = out + CTXN; }
    else if ((long long)out_size == ATTN)   { ctx = nullptr; attn = out; }
    else                                    { ctx = out; attn = out; }

    cudaFuncSetAttribute(score_mma, cudaFuncAttributeMaxDynamicSharedMemorySize, SMEM_TOT);
    score_mma<<<dim3(16, 32), 256, SMEM_TOT>>>(Q, K, Er, attn);

    const int smB = (8192 + 8192 + 64) * (int)sizeof(float);
    cudaFuncSetAttribute(pv_kernel, cudaFuncAttributeMaxDynamicSharedMemorySize, smB);
    pv_kernel<<<dim3(32, 32), 128, smB>>>(V, ctx, attn);
}